// round 15
// baseline (speedup 1.0000x reference)
#include <cuda_runtime.h>
#include <math.h>

#define T_STEPS 2048
#define BATCH   64
#define IN_DIM  256
#define HID     512
#define NCTA    128
#define NTHREADS 1024
#define KSPLIT  16
#define STAGE_S 66
#define SMEM_FLOATS (768*16 + 1024*16 + 256*STAGE_S + 16 + 16 + 256 + 256 + 4 + 4*66)
#define HB (HID * BATCH)

__device__ float g_xT [(size_t)T_STEPS * IN_DIM * BATCH + 128];  // [t][k][b]
__device__ float g_h1T[2 * HB + 128];                            // slot s at s*HB
__device__ float g_h2T[2 * HB + 128];
__device__ float g_outacc[T_STEPS * BATCH];
__device__ unsigned g_c0, g_s0, g_c1, g_s1, g_c2, g_s2;          // monotonic sense barriers

__device__ __forceinline__ unsigned ld_acq(unsigned* p) {
    unsigned v; asm volatile("ld.acquire.gpu.u32 %0, [%1];" : "=r"(v) : "l"(p)); return v;
}
__device__ __forceinline__ void fma2(unsigned long long& d, unsigned long long a, unsigned long long b) {
    asm("fma.rn.f32x2 %0, %1, %2, %0;" : "+l"(d) : "l"(a), "l"(b));
}
__device__ __forceinline__ unsigned long long dupf(float a) {
    unsigned long long r; asm("mov.b64 %0, {%1, %1};" : "=l"(r) : "f"(a)); return r;
}
__device__ __forceinline__ float fex2(float x) { float r; asm("ex2.approx.f32 %0, %1;" : "=f"(r) : "f"(x)); return r; }
__device__ __forceinline__ float frcp(float x) { float r; asm("rcp.approx.f32 %0, %1;" : "=f"(r) : "f"(x)); return r; }
__device__ __forceinline__ float fsig(float x)  { return frcp(1.0f + fex2(-1.4426950408889634f * x)); }
__device__ __forceinline__ float ftanh(float x) { return fmaf(2.0f, frcp(1.0f + fex2(-2.8853900817779268f * x)), -1.0f); }

__device__ __forceinline__ void bar_arrive(unsigned* cnt, unsigned* sense) {
    if (threadIdx.x == 0) {
        __threadfence();
        if (atomicAdd(cnt, 1) == NCTA - 1) { *cnt = 0; __threadfence(); atomicAdd(sense, 1); }
    }
}
__device__ __forceinline__ void bar_wait(unsigned* sense, unsigned target) {
    if (threadIdx.x == 0) { while ((int)(ld_acq(sense) - target) < 0) { } }
    __syncthreads();
}

// Lane tile: 4 rows (rg) x 4 batches (2 packed pairs). Warp = (K-slice, batch half).
// rot: CTA-dependent rotation of the k order — de-hotspots L2 (without it, all
// 128 CTAs request the SAME 128B line simultaneously; one LTS slice serializes
// 128 responses while others idle).
template<int NK>
__device__ __forceinline__ void accum(unsigned long long acc[8],
                                      const float* __restrict__ hT,
                                      const float* wsT, int rg, int bgoff, int rot) {
    const ulonglong2* hp = reinterpret_cast<const ulonglong2*>(hT + bgoff);
#pragma unroll 4
    for (int k = 0; k < NK; k++) {
        int kk = (k + rot) & (NK - 1);
        float4 w4 = *reinterpret_cast<const float4*>(wsT + kk * 16 + rg * 4);
        ulonglong2 h = __ldcg(hp + kk * 16);       // 64 floats/row = 16 ulonglong2
        unsigned long long w0 = dupf(w4.x), w1 = dupf(w4.y);
        unsigned long long w2 = dupf(w4.z), w3 = dupf(w4.w);
        fma2(acc[0], h.x, w0); fma2(acc[1], h.y, w0);
        fma2(acc[2], h.x, w1); fma2(acc[3], h.y, w1);
        fma2(acc[4], h.x, w2); fma2(acc[5], h.y, w2);
        fma2(acc[6], h.x, w3); fma2(acc[7], h.y, w3);
    }
}

__device__ __forceinline__ void dump_stage(float* stage, unsigned long long acc[8],
                                           int ks, int rg, int bgoff) {
#pragma unroll
    for (int i = 0; i < 4; i++) {
        float2* sp = reinterpret_cast<float2*>(stage + (ks * 16 + rg * 4 + i) * STAGE_S + bgoff);
#pragma unroll
        for (int p = 0; p < 2; p++) {
            unsigned long long a = acc[i * 2 + p];
            sp[p] = make_float2(__uint_as_float((unsigned)a), __uint_as_float((unsigned)(a >> 32)));
        }
    }
}

__global__ void __launch_bounds__(NTHREADS, 1)
lstm_all(const float* __restrict__ input,
         const float* __restrict__ Wih1, const float* __restrict__ Whh1,
         const float* __restrict__ bih1, const float* __restrict__ bhh1,
         const float* __restrict__ Wih2, const float* __restrict__ Whh2,
         const float* __restrict__ bih2, const float* __restrict__ bhh2,
         const float* __restrict__ Wout, const float* __restrict__ bout,
         float* __restrict__ out) {
    extern __shared__ float sm[];
    float* ws1T   = sm;                        // [768][16]
    float* ws2T   = ws1T + 768 * 16;           // [1024][16]
    float* stage  = ws2T + 1024 * 16;          // [256][STAGE_S] (also transpose scratch)
    float* bias1  = stage + 256 * STAGE_S;
    float* bias2  = bias1 + 16;
    float* c1     = bias2 + 16;
    float* c2     = c1 + 256;
    float* wout_s = c2 + 256;                  // [4]
    float* outred = wout_s + 4;                // [4][66]

    const int tid = threadIdx.x, j0 = blockIdx.x * 4;
    const int wid = tid >> 5, lane = tid & 31;
    const int ks = wid & 15;                   // K-slice 0..15
    const int bs = wid >> 4;                   // batch half 0..1
    const int rg = lane >> 3, bg = lane & 7;
    const int bgoff = bs * 32 + bg * 4;
    const int rot32 = blockIdx.x & 31;         // k-order rotation (de-hotspot)
    const int rot16 = blockIdx.x & 15;

    const unsigned base0 = ld_acq(&g_s0);
    const unsigned base1 = ld_acq(&g_s1);
    const unsigned base2 = ld_acq(&g_s2);

    // ---- phase 0a: zero out-accumulator ----
    g_outacc[blockIdx.x * 1024 + tid] = 0.0f;

    // ---- phase 0b: transpose x[t][b][i] -> g_xT[t][i][b] ----
    {
        const int q = tid >> 8;
        const int ltid = tid & 255;
        const int tx = ltid & 31, ty = ltid >> 5;
        float* tile = stage + q * (32 * 33);
        for (int tp = blockIdx.x * 4 + q; tp < 32768; tp += NCTA * 4) {
            int t = tp >> 4, i0 = (tp & 7) * 32, b0 = ((tp >> 3) & 1) * 32;
#pragma unroll
            for (int r = 0; r < 32; r += 8)
                tile[(ty + r) * 33 + tx] =
                    input[((size_t)t * BATCH + b0 + ty + r) * IN_DIM + i0 + tx];
            __syncthreads();
#pragma unroll
            for (int r = 0; r < 32; r += 8)
                g_xT[((size_t)t * IN_DIM + i0 + ty + r) * BATCH + b0 + tx] = tile[tx * 33 + ty + r];
            __syncthreads();
        }
    }

    // ---- phase 0c: weights + biases into SMEM ----
    for (int lr = 0; lr < 16; lr++) {
        int grow = (lr >> 2) * HID + j0 + (lr & 3);
        const float* a = Wih1 + (size_t)grow * IN_DIM;
        const float* b = Whh1 + (size_t)grow * HID;
        const float* c = Wih2 + (size_t)grow * HID;
        const float* d = Whh2 + (size_t)grow * HID;
        for (int k = tid; k < IN_DIM; k += NTHREADS) ws1T[k * 16 + lr]            = a[k];
        for (int k = tid; k < HID;    k += NTHREADS) ws1T[(IN_DIM + k) * 16 + lr] = b[k];
        for (int k = tid; k < HID;    k += NTHREADS) ws2T[k * 16 + lr]            = c[k];
        for (int k = tid; k < HID;    k += NTHREADS) ws2T[(HID + k) * 16 + lr]    = d[k];
    }
    if (tid < 16) {
        int grow = (tid >> 2) * HID + j0 + (tid & 3);
        bias1[tid] = bih1[grow] + bhh1[grow];
        bias2[tid] = bih2[grow] + bhh2[grow];
    }
    if (tid < 256) { c1[tid] = 0.0f; c2[tid] = 0.0f; }
    if (tid < 4) wout_s[tid] = Wout[j0 + tid];
    __syncthreads();

    bar_arrive(&g_c0, &g_s0);
    bar_wait(&g_s0, base0 + 1);

    unsigned long long acc1[8], acc2[8];
#pragma unroll
    for (int i = 0; i < 8; i++) acc1[i] = 0ull;
    accum<16>(acc1, g_xT + (size_t)(ks * 16) * BATCH, ws1T + (ks * 16) * 16, rg, bgoff, rot16);

    for (int t = 0; t < T_STEPS; t++) {
        // ---- finish layer-1 gates: h1(t-1) contribution ----
        if (t > 0)
            accum<32>(acc1, g_h1T + ((t - 1) & 1) * HB + (size_t)(ks * 32) * BATCH,
                      ws1T + (IN_DIM + ks * 32) * 16, rg, bgoff, rot32);
        dump_stage(stage, acc1, ks, rg, bgoff);
        __syncthreads();
        if (tid < 256) {
            int jj = tid >> 6, b = tid & 63;
            float gv[4];
#pragma unroll
            for (int g = 0; g < 4; g++) {
                float s = bias1[g * 4 + jj];
#pragma unroll
                for (int w = 0; w < KSPLIT; w++) s += stage[(w * 16 + g * 4 + jj) * STAGE_S + b];
                gv[g] = s;
            }
            float c = fsig(gv[1]) * c1[tid] + fsig(gv[0]) * ftanh(gv[2]);
            c1[tid] = c;
            g_h1T[(t & 1) * HB + (size_t)(j0 + jj) * BATCH + b] = fsig(gv[3]) * ftanh(c);
        }
        __syncthreads();
        bar_arrive(&g_c1, &g_s1);

        // ---- layer-2 independent part: h2(t-1) (hides bar1 wait) ----
#pragma unroll
        for (int i = 0; i < 8; i++) acc2[i] = 0ull;
        if (t > 0)
            accum<32>(acc2, g_h2T + ((t - 1) & 1) * HB + (size_t)(ks * 32) * BATCH,
                      ws2T + (HID + ks * 32) * 16, rg, bgoff, rot32);
        bar_wait(&g_s1, base1 + t + 1);

        // ---- layer-2 dependent part: h1(t) ----
        accum<32>(acc2, g_h1T + (t & 1) * HB + (size_t)(ks * 32) * BATCH,
                  ws2T + (ks * 32) * 16, rg, bgoff, rot32);
        dump_stage(stage, acc2, ks, rg, bgoff);
        __syncthreads();
        if (tid < 256) {
            int jj = tid >> 6, b = tid & 63;
            float gv[4];
#pragma unroll
            for (int g = 0; g < 4; g++) {
                float s = bias2[g * 4 + jj];
#pragma unroll
                for (int w = 0; w < KSPLIT; w++) s += stage[(w * 16 + g * 4 + jj) * STAGE_S + b];
                gv[g] = s;
            }
            float c = fsig(gv[1]) * c2[tid] + fsig(gv[0]) * ftanh(gv[2]);
            c2[tid] = c;
            float h = fsig(gv[3]) * ftanh(c);
            g_h2T[(t & 1) * HB + (size_t)(j0 + jj) * BATCH + b] = h;
            outred[jj * 66 + b] = h * wout_s[jj];
        }
        __syncthreads();
        if (tid < 64) {
            float v = outred[tid] + outred[66 + tid] + outred[132 + tid] + outred[198 + tid];
            atomicAdd(&g_outacc[t * BATCH + tid], v);
        }
        bar_arrive(&g_c2, &g_s2);

        // ---- next step's independent part: x(t+1) (hides bar2 wait) ----
#pragma unroll
        for (int i = 0; i < 8; i++) acc1[i] = 0ull;
        if (t + 1 < T_STEPS)
            accum<16>(acc1, g_xT + (size_t)(t + 1) * IN_DIM * BATCH + (size_t)(ks * 16) * BATCH,
                      ws1T + (ks * 16) * 16, rg, bgoff, rot16);
        bar_wait(&g_s2, base2 + t + 1);
    }

    // ---- final: all REDs visible everywhere, then fused output head ----
    __threadfence();
    __syncthreads();
    bar_arrive(&g_c0, &g_s0);
    bar_wait(&g_s0, base0 + 2);
    {
        int i0 = blockIdx.x * 1024 + tid;
        out[i0] = fsig(__ldcg(&g_outacc[i0]) + bout[0]);
    }
}

extern "C" void kernel_launch(void* const* d_in, const int* in_sizes, int n_in,
                              void* d_out, int out_size) {
    const float* input = (const float*)d_in[0];
    const float* Wih1 = (const float*)d_in[1];
    const float* Whh1 = (const float*)d_in[2];
    const float* bih1 = (const float*)d_in[3];
    const float* bhh1 = (const float*)d_in[4];
    const float* Wih2 = (const float*)d_in[5];
    const float* Whh2 = (const float*)d_in[6];
    const float* bih2 = (const float*)d_in[7];
    const float* bhh2 = (const float*)d_in[8];
    const float* Wout = (const float*)d_in[9];
    const float* bout = (const float*)d_in[10];

    int smem_bytes = SMEM_FLOATS * (int)sizeof(float);   // ~186 KB
    cudaFuncSetAttribute(lstm_all,
                         cudaFuncAttributeMaxDynamicSharedMemorySize, smem_bytes);
    lstm_all<<<NCTA, NTHREADS, smem_bytes>>>(
        input, Wih1, Whh1, bih1, bhh1, Wih2, Whh2, bih2, bhh2,
        Wout, bout, (float*)d_out);
}

// round 16
// speedup vs baseline: 1.0183x; 1.0183x over previous
#include <cuda_runtime.h>
#include <math.h>

#define T_STEPS 2048
#define BATCH   64
#define IN_DIM  256
#define HID     512
#define NCTA    128
#define NTHREADS 1024
#define KSPLIT  16
#define STAGE_S 66
#define SMEM_FLOATS (768*16 + 1024*16 + 256*STAGE_S + 16 + 16 + 256 + 256 + 4 + 4*66)
#define HB (HID * BATCH)

__device__ float g_xT [(size_t)T_STEPS * IN_DIM * BATCH + 128];  // [t][k][b]
__device__ float g_h1T[2 * HB + 128];                            // slot s at s*HB
__device__ float g_h2T[2 * HB + 128];
__device__ float g_outacc[T_STEPS * BATCH];
__device__ unsigned g_c0, g_s0, g_c1, g_s1, g_c2, g_s2;          // monotonic sense barriers

__device__ __forceinline__ unsigned ld_acq(unsigned* p) {
    unsigned v; asm volatile("ld.acquire.gpu.u32 %0, [%1];" : "=r"(v) : "l"(p)); return v;
}
__device__ __forceinline__ void fma2(unsigned long long& d, unsigned long long a, unsigned long long b) {
    asm("fma.rn.f32x2 %0, %1, %2, %0;" : "+l"(d) : "l"(a), "l"(b));
}
__device__ __forceinline__ unsigned long long dupf(float a) {
    unsigned long long r; asm("mov.b64 %0, {%1, %1};" : "=l"(r) : "f"(a)); return r;
}
__device__ __forceinline__ float fex2(float x) { float r; asm("ex2.approx.f32 %0, %1;" : "=f"(r) : "f"(x)); return r; }
__device__ __forceinline__ float frcp(float x) { float r; asm("rcp.approx.f32 %0, %1;" : "=f"(r) : "f"(x)); return r; }
__device__ __forceinline__ float fsig(float x)  { return frcp(1.0f + fex2(-1.4426950408889634f * x)); }
__device__ __forceinline__ float ftanh(float x) { return fmaf(2.0f, frcp(1.0f + fex2(-2.8853900817779268f * x)), -1.0f); }

#define EPI_BAR() asm volatile("bar.sync 1, 256;" ::: "memory")

__device__ __forceinline__ void bar_arrive(unsigned* cnt, unsigned* sense) {
    if (threadIdx.x == 0) {
        __threadfence();
        if (atomicAdd(cnt, 1) == NCTA - 1) { *cnt = 0; __threadfence(); atomicAdd(sense, 1); }
    }
}
__device__ __forceinline__ void bar_wait(unsigned* sense, unsigned target) {
    if (threadIdx.x == 0) { while ((int)(ld_acq(sense) - target) < 0) { } }
    __syncthreads();
}

// Lane tile: 4 rows (rg) x 4 batches (2 packed pairs). Warp = (K-slice, batch half).
template<int NK>
__device__ __forceinline__ void accum(unsigned long long acc[8],
                                      const float* __restrict__ hT,
                                      const float* wsT, int rg, int bgoff) {
    const ulonglong2* hp = reinterpret_cast<const ulonglong2*>(hT + bgoff);
#pragma unroll 4
    for (int k = 0; k < NK; k++) {
        float4 w4 = *reinterpret_cast<const float4*>(wsT + k * 16 + rg * 4);
        ulonglong2 h = __ldcg(hp + k * 16);        // 64 floats/row = 16 ulonglong2
        unsigned long long w0 = dupf(w4.x), w1 = dupf(w4.y);
        unsigned long long w2 = dupf(w4.z), w3 = dupf(w4.w);
        fma2(acc[0], h.x, w0); fma2(acc[1], h.y, w0);
        fma2(acc[2], h.x, w1); fma2(acc[3], h.y, w1);
        fma2(acc[4], h.x, w2); fma2(acc[5], h.y, w2);
        fma2(acc[6], h.x, w3); fma2(acc[7], h.y, w3);
    }
}

__device__ __forceinline__ void dump_stage(float* stage, unsigned long long acc[8],
                                           int ks, int rg, int bgoff) {
#pragma unroll
    for (int i = 0; i < 4; i++) {
        float2* sp = reinterpret_cast<float2*>(stage + (ks * 16 + rg * 4 + i) * STAGE_S + bgoff);
#pragma unroll
        for (int p = 0; p < 2; p++) {
            unsigned long long a = acc[i * 2 + p];
            sp[p] = make_float2(__uint_as_float((unsigned)a), __uint_as_float((unsigned)(a >> 32)));
        }
    }
}

__global__ void __launch_bounds__(NTHREADS, 1)
lstm_all(const float* __restrict__ input,
         const float* __restrict__ Wih1, const float* __restrict__ Whh1,
         const float* __restrict__ bih1, const float* __restrict__ bhh1,
         const float* __restrict__ Wih2, const float* __restrict__ Whh2,
         const float* __restrict__ bih2, const float* __restrict__ bhh2,
         const float* __restrict__ Wout, const float* __restrict__ bout,
         float* __restrict__ out) {
    extern __shared__ float sm[];
    float* ws1T   = sm;                        // [768][16]
    float* ws2T   = ws1T + 768 * 16;           // [1024][16]
    float* stage  = ws2T + 1024 * 16;          // [256][STAGE_S] (also transpose scratch)
    float* bias1  = stage + 256 * STAGE_S;
    float* bias2  = bias1 + 16;
    float* c1     = bias2 + 16;
    float* c2     = c1 + 256;
    float* wout_s = c2 + 256;                  // [4]
    float* outred = wout_s + 4;                // [4][66]

    const int tid = threadIdx.x, j0 = blockIdx.x * 4;
    const int wid = tid >> 5, lane = tid & 31;
    const int ks = wid & 15;                   // K-slice 0..15
    const int bs = wid >> 4;                   // batch half 0..1
    const int rg = lane >> 3, bg = lane & 7;
    const int bgoff = bs * 32 + bg * 4;

    const unsigned base0 = ld_acq(&g_s0);
    const unsigned base1 = ld_acq(&g_s1);
    const unsigned base2 = ld_acq(&g_s2);

    // ---- phase 0a: zero out-accumulator ----
    g_outacc[blockIdx.x * 1024 + tid] = 0.0f;

    // ---- phase 0b: transpose x[t][b][i] -> g_xT[t][i][b] ----
    {
        const int q = tid >> 8;
        const int ltid = tid & 255;
        const int tx = ltid & 31, ty = ltid >> 5;
        float* tile = stage + q * (32 * 33);
        for (int tp = blockIdx.x * 4 + q; tp < 32768; tp += NCTA * 4) {
            int t = tp >> 4, i0 = (tp & 7) * 32, b0 = ((tp >> 3) & 1) * 32;
#pragma unroll
            for (int r = 0; r < 32; r += 8)
                tile[(ty + r) * 33 + tx] =
                    input[((size_t)t * BATCH + b0 + ty + r) * IN_DIM + i0 + tx];
            __syncthreads();
#pragma unroll
            for (int r = 0; r < 32; r += 8)
                g_xT[((size_t)t * IN_DIM + i0 + ty + r) * BATCH + b0 + tx] = tile[tx * 33 + ty + r];
            __syncthreads();
        }
    }

    // ---- phase 0c: weights + biases into SMEM ----
    for (int lr = 0; lr < 16; lr++) {
        int grow = (lr >> 2) * HID + j0 + (lr & 3);
        const float* a = Wih1 + (size_t)grow * IN_DIM;
        const float* b = Whh1 + (size_t)grow * HID;
        const float* c = Wih2 + (size_t)grow * HID;
        const float* d = Whh2 + (size_t)grow * HID;
        for (int k = tid; k < IN_DIM; k += NTHREADS) ws1T[k * 16 + lr]            = a[k];
        for (int k = tid; k < HID;    k += NTHREADS) ws1T[(IN_DIM + k) * 16 + lr] = b[k];
        for (int k = tid; k < HID;    k += NTHREADS) ws2T[k * 16 + lr]            = c[k];
        for (int k = tid; k < HID;    k += NTHREADS) ws2T[(HID + k) * 16 + lr]    = d[k];
    }
    if (tid < 16) {
        int grow = (tid >> 2) * HID + j0 + (tid & 3);
        bias1[tid] = bih1[grow] + bhh1[grow];
        bias2[tid] = bih2[grow] + bhh2[grow];
    }
    if (tid < 256) { c1[tid] = 0.0f; c2[tid] = 0.0f; }
    if (tid < 4) wout_s[tid] = Wout[j0 + tid];
    __syncthreads();

    bar_arrive(&g_c0, &g_s0);
    bar_wait(&g_s0, base0 + 1);

    unsigned long long acc1[8], acc2[8];
#pragma unroll
    for (int i = 0; i < 8; i++) acc1[i] = 0ull;
    accum<16>(acc1, g_xT + (size_t)(ks * 16) * BATCH, ws1T + (ks * 16) * 16, rg, bgoff);

    for (int t = 0; t < T_STEPS; t++) {
        // ---- finish layer-1 gates: h1(t-1) contribution ----
        if (t > 0)
            accum<32>(acc1, g_h1T + ((t - 1) & 1) * HB + (size_t)(ks * 32) * BATCH,
                      ws1T + (IN_DIM + ks * 32) * 16, rg, bgoff);
        dump_stage(stage, acc1, ks, rg, bgoff);
        __syncthreads();
        // epilogue 1 on warps 0-7 ONLY; warps 8-31 fall through to acc2 part A.
        // Stage reuse is safe: epi warps finish before joining bar_wait's
        // __syncthreads below, which precedes the next dump_stage.
        if (tid < 256) {
            int jj = tid >> 6, b = tid & 63;
            float gv[4];
#pragma unroll
            for (int g = 0; g < 4; g++) {
                float s = bias1[g * 4 + jj];
#pragma unroll
                for (int w = 0; w < KSPLIT; w++) s += stage[(w * 16 + g * 4 + jj) * STAGE_S + b];
                gv[g] = s;
            }
            float c = fsig(gv[1]) * c1[tid] + fsig(gv[0]) * ftanh(gv[2]);
            c1[tid] = c;
            g_h1T[(t & 1) * HB + (size_t)(j0 + jj) * BATCH + b] = fsig(gv[3]) * ftanh(c);
            EPI_BAR();                          // all epi h1-writes done
            bar_arrive(&g_c1, &g_s1);           // tid0: fence + publish h1(t)
        }

        // ---- layer-2 independent part: h2(t-1) (overlaps epi1 + hides bar1 wait) ----
#pragma unroll
        for (int i = 0; i < 8; i++) acc2[i] = 0ull;
        if (t > 0)
            accum<32>(acc2, g_h2T + ((t - 1) & 1) * HB + (size_t)(ks * 32) * BATCH,
                      ws2T + (HID + ks * 32) * 16, rg, bgoff);
        bar_wait(&g_s1, base1 + t + 1);

        // ---- layer-2 dependent part: h1(t) ----
        accum<32>(acc2, g_h1T + (t & 1) * HB + (size_t)(ks * 32) * BATCH,
                  ws2T + (ks * 32) * 16, rg, bgoff);
        dump_stage(stage, acc2, ks, rg, bgoff);
        __syncthreads();
        // epilogue 2 on warps 0-7 ONLY; warps 8-31 fall through to x(t+1).
        if (tid < 256) {
            int jj = tid >> 6, b = tid & 63;
            float gv[4];
#pragma unroll
            for (int g = 0; g < 4; g++) {
                float s = bias2[g * 4 + jj];
#pragma unroll
                for (int w = 0; w < KSPLIT; w++) s += stage[(w * 16 + g * 4 + jj) * STAGE_S + b];
                gv[g] = s;
            }
            float c = fsig(gv[1]) * c2[tid] + fsig(gv[0]) * ftanh(gv[2]);
            c2[tid] = c;
            float h = fsig(gv[3]) * ftanh(c);
            g_h2T[(t & 1) * HB + (size_t)(j0 + jj) * BATCH + b] = h;
            outred[jj * 66 + b] = h * wout_s[jj];
            EPI_BAR();                          // h2 + outred writes done
            if (tid < 64) {
                float v = outred[tid] + outred[66 + tid] + outred[132 + tid] + outred[198 + tid];
                atomicAdd(&g_outacc[t * BATCH + tid], v);
            }
            bar_arrive(&g_c2, &g_s2);           // tid0: fence + publish h2(t)
        }

        // ---- next step's independent part: x(t+1) (overlaps epi2 + hides bar2 wait) ----
#pragma unroll
        for (int i = 0; i < 8; i++) acc1[i] = 0ull;
        if (t + 1 < T_STEPS)
            accum<16>(acc1, g_xT + (size_t)(t + 1) * IN_DIM * BATCH + (size_t)(ks * 16) * BATCH,
                      ws1T + (ks * 16) * 16, rg, bgoff);
        bar_wait(&g_s2, base2 + t + 1);
    }

    // ---- final: all REDs visible everywhere, then fused output head ----
    __threadfence();
    __syncthreads();
    bar_arrive(&g_c0, &g_s0);
    bar_wait(&g_s0, base0 + 2);
    {
        int i0 = blockIdx.x * 1024 + tid;
        out[i0] = fsig(__ldcg(&g_outacc[i0]) + bout[0]);
    }
}

extern "C" void kernel_launch(void* const* d_in, const int* in_sizes, int n_in,
                              void* d_out, int out_size) {
    const float* input = (const float*)d_in[0];
    const float* Wih1 = (const float*)d_in[1];
    const float* Whh1 = (const float*)d_in[2];
    const float* bih1 = (const float*)d_in[3];
    const float* bhh1 = (const float*)d_in[4];
    const float* Wih2 = (const float*)d_in[5];
    const float* Whh2 = (const float*)d_in[6];
    const float* bih2 = (const float*)d_in[7];
    const float* bhh2 = (const float*)d_in[8];
    const float* Wout = (const float*)d_in[9];
    const float* bout = (const float*)d_in[10];

    int smem_bytes = SMEM_FLOATS * (int)sizeof(float);   // ~186 KB
    cudaFuncSetAttribute(lstm_all,
                         cudaFuncAttributeMaxDynamicSharedMemorySize, smem_bytes);
    lstm_all<<<NCTA, NTHREADS, smem_bytes>>>(
        input, Wih1, Whh1, bih1, bhh1, Wih2, Whh2, bih2, bhh2,
        Wout, bout, (float*)d_out);
}

// round 17
// speedup vs baseline: 1.1853x; 1.1640x over previous
#include <cuda_runtime.h>
#include <math.h>

#define T_STEPS 2048
#define BATCH   64
#define IN_DIM  256
#define HID     512
#define NCTA    256
#define NTHREADS 512
#define KSPLIT  16
#define STAGE_S 66
// ws1T 768*8, ws2T 1024*8, stage 128*66, b1 8, b2 8, c1 128, c2 128, wo 2, ored 2*66
#define SMEM_FLOATS (768*8 + 1024*8 + 128*STAGE_S + 8 + 8 + 128 + 128 + 2 + 2*66)
#define HB (HID * BATCH)

__device__ float g_xT [(size_t)T_STEPS * IN_DIM * BATCH + 128];  // [t][k][b]
__device__ float g_h1T[2 * HB + 128];                            // slot s at s*HB
__device__ float g_h2T[2 * HB + 128];
__device__ float g_outacc[T_STEPS * BATCH];
__device__ unsigned g_c0, g_s0, g_c1, g_s1, g_c2, g_s2;          // monotonic sense barriers

__device__ __forceinline__ unsigned ld_acq(unsigned* p) {
    unsigned v; asm volatile("ld.acquire.gpu.u32 %0, [%1];" : "=r"(v) : "l"(p)); return v;
}
__device__ __forceinline__ void fma2(unsigned long long& d, unsigned long long a, unsigned long long b) {
    asm("fma.rn.f32x2 %0, %1, %2, %0;" : "+l"(d) : "l"(a), "l"(b));
}
__device__ __forceinline__ unsigned long long dupf(float a) {
    unsigned long long r; asm("mov.b64 %0, {%1, %1};" : "=l"(r) : "f"(a)); return r;
}
__device__ __forceinline__ float fex2(float x) { float r; asm("ex2.approx.f32 %0, %1;" : "=f"(r) : "f"(x)); return r; }
__device__ __forceinline__ float frcp(float x) { float r; asm("rcp.approx.f32 %0, %1;" : "=f"(r) : "f"(x)); return r; }
__device__ __forceinline__ float fsig(float x)  { return frcp(1.0f + fex2(-1.4426950408889634f * x)); }
__device__ __forceinline__ float ftanh(float x) { return fmaf(2.0f, frcp(1.0f + fex2(-2.8853900817779268f * x)), -1.0f); }

__device__ __forceinline__ void bar_arrive(unsigned* cnt, unsigned* sense) {
    if (threadIdx.x == 0) {
        __threadfence();
        if (atomicAdd(cnt, 1) == NCTA - 1) { *cnt = 0; __threadfence(); atomicAdd(sense, 1); }
    }
}
__device__ __forceinline__ void bar_wait(unsigned* sense, unsigned target) {
    if (threadIdx.x == 0) { while ((int)(ld_acq(sense) - target) < 0) { } }
    __syncthreads();
}

// Lane tile: 4 rows (of this CTA's 8) x 4 batches (2 packed pairs).
// Warp = K-slice ks; lane = (rg in 0..1 picks 4 rows, bg in 0..15 picks 4 batches).
template<int NK>
__device__ __forceinline__ void accum(unsigned long long acc[8],
                                      const float* __restrict__ hT,
                                      const float* wsT, int rg, int bgoff) {
    const ulonglong2* hp = reinterpret_cast<const ulonglong2*>(hT + bgoff);
#pragma unroll 4
    for (int k = 0; k < NK; k++) {
        float4 w4 = *reinterpret_cast<const float4*>(wsT + k * 8 + rg * 4);
        ulonglong2 h = __ldcg(hp + k * 16);        // 64 floats/row = 16 ulonglong2
        unsigned long long w0 = dupf(w4.x), w1 = dupf(w4.y);
        unsigned long long w2 = dupf(w4.z), w3 = dupf(w4.w);
        fma2(acc[0], h.x, w0); fma2(acc[1], h.y, w0);
        fma2(acc[2], h.x, w1); fma2(acc[3], h.y, w1);
        fma2(acc[4], h.x, w2); fma2(acc[5], h.y, w2);
        fma2(acc[6], h.x, w3); fma2(acc[7], h.y, w3);
    }
}

__device__ __forceinline__ void dump_stage(float* stage, unsigned long long acc[8],
                                           int ks, int rg, int bgoff) {
#pragma unroll
    for (int i = 0; i < 4; i++) {
        float2* sp = reinterpret_cast<float2*>(stage + (ks * 8 + rg * 4 + i) * STAGE_S + bgoff);
#pragma unroll
        for (int p = 0; p < 2; p++) {
            unsigned long long a = acc[i * 2 + p];
            sp[p] = make_float2(__uint_as_float((unsigned)a), __uint_as_float((unsigned)(a >> 32)));
        }
    }
}

__global__ void __launch_bounds__(NTHREADS, 2)
lstm_all(const float* __restrict__ input,
         const float* __restrict__ Wih1, const float* __restrict__ Whh1,
         const float* __restrict__ bih1, const float* __restrict__ bhh1,
         const float* __restrict__ Wih2, const float* __restrict__ Whh2,
         const float* __restrict__ bih2, const float* __restrict__ bhh2,
         const float* __restrict__ Wout, const float* __restrict__ bout,
         float* __restrict__ out) {
    extern __shared__ float sm[];
    float* ws1T   = sm;                        // [768][8]
    float* ws2T   = ws1T + 768 * 8;            // [1024][8]
    float* stage  = ws2T + 1024 * 8;           // [128][STAGE_S] (also transpose scratch)
    float* bias1  = stage + 128 * STAGE_S;     // [8]
    float* bias2  = bias1 + 8;                 // [8]
    float* c1     = bias2 + 8;                 // [128]
    float* c2     = c1 + 128;                  // [128]
    float* wout_s = c2 + 128;                  // [2]
    float* outred = wout_s + 2;                // [2][66]

    const int tid = threadIdx.x, j0 = blockIdx.x * 2;   // this CTA's 2 hidden units
    const int wid = tid >> 5, lane = tid & 31;
    const int ks = wid;                        // K-slice 0..15
    const int rg = lane >> 4;                  // row group (2 x 4 rows)
    const int bg = lane & 15;                  // batch group (16 x 4 batches)
    const int bgoff = bg * 4;

    const unsigned base0 = ld_acq(&g_s0);
    const unsigned base1 = ld_acq(&g_s1);
    const unsigned base2 = ld_acq(&g_s2);

    // ---- phase 0a: zero out-accumulator (512 per CTA) ----
    g_outacc[blockIdx.x * 512 + tid] = 0.0f;

    // ---- phase 0b: transpose x[t][b][i] -> g_xT[t][i][b] ----
    {
        const int q = tid >> 8;                // two 256-thread groups
        const int ltid = tid & 255;
        const int tx = ltid & 31, ty = ltid >> 5;
        float* tile = stage + q * (32 * 33);
        for (int tp = blockIdx.x * 2 + q; tp < 32768; tp += NCTA * 2) {
            int t = tp >> 4, i0 = (tp & 7) * 32, b0 = ((tp >> 3) & 1) * 32;
#pragma unroll
            for (int r = 0; r < 32; r += 8)
                tile[(ty + r) * 33 + tx] =
                    input[((size_t)t * BATCH + b0 + ty + r) * IN_DIM + i0 + tx];
            __syncthreads();
#pragma unroll
            for (int r = 0; r < 32; r += 8)
                g_xT[((size_t)t * IN_DIM + i0 + ty + r) * BATCH + b0 + tx] = tile[tx * 33 + ty + r];
            __syncthreads();
        }
    }

    // ---- phase 0c: weights + biases into SMEM (8 rows: gate = lr>>1, unit = lr&1) ----
    for (int lr = 0; lr < 8; lr++) {
        int grow = (lr >> 1) * HID + j0 + (lr & 1);
        const float* a = Wih1 + (size_t)grow * IN_DIM;
        const float* b = Whh1 + (size_t)grow * HID;
        const float* c = Wih2 + (size_t)grow * HID;
        const float* d = Whh2 + (size_t)grow * HID;
        for (int k = tid; k < IN_DIM; k += NTHREADS) ws1T[k * 8 + lr]            = a[k];
        for (int k = tid; k < HID;    k += NTHREADS) ws1T[(IN_DIM + k) * 8 + lr] = b[k];
        for (int k = tid; k < HID;    k += NTHREADS) ws2T[k * 8 + lr]            = c[k];
        for (int k = tid; k < HID;    k += NTHREADS) ws2T[(HID + k) * 8 + lr]    = d[k];
    }
    if (tid < 8) {
        int grow = (tid >> 1) * HID + j0 + (tid & 1);
        bias1[tid] = bih1[grow] + bhh1[grow];
        bias2[tid] = bih2[grow] + bhh2[grow];
    }
    if (tid < 128) { c1[tid] = 0.0f; c2[tid] = 0.0f; }
    if (tid < 2) wout_s[tid] = Wout[j0 + tid];
    __syncthreads();

    bar_arrive(&g_c0, &g_s0);
    bar_wait(&g_s0, base0 + 1);

    unsigned long long acc1[8], acc2[8];
#pragma unroll
    for (int i = 0; i < 8; i++) acc1[i] = 0ull;
    accum<16>(acc1, g_xT + (size_t)(ks * 16) * BATCH, ws1T + (ks * 16) * 8, rg, bgoff);

    for (int t = 0; t < T_STEPS; t++) {
        // ---- finish layer-1 gates: h1(t-1) contribution ----
        if (t > 0)
            accum<32>(acc1, g_h1T + ((t - 1) & 1) * HB + (size_t)(ks * 32) * BATCH,
                      ws1T + (IN_DIM + ks * 32) * 8, rg, bgoff);
        dump_stage(stage, acc1, ks, rg, bgoff);
        __syncthreads();
        if (tid < 128) {
            int jj = tid >> 6, b = tid & 63;
            float gv[4];
#pragma unroll
            for (int g = 0; g < 4; g++) {
                float s = bias1[g * 2 + jj];
#pragma unroll
                for (int w = 0; w < KSPLIT; w++) s += stage[(w * 8 + g * 2 + jj) * STAGE_S + b];
                gv[g] = s;
            }
            float c = fsig(gv[1]) * c1[tid] + fsig(gv[0]) * ftanh(gv[2]);
            c1[tid] = c;
            g_h1T[(t & 1) * HB + (size_t)(j0 + jj) * BATCH + b] = fsig(gv[3]) * ftanh(c);
        }
        __syncthreads();
        bar_arrive(&g_c1, &g_s1);

        // ---- layer-2 independent part: h2(t-1) (hides bar1 wait) ----
#pragma unroll
        for (int i = 0; i < 8; i++) acc2[i] = 0ull;
        if (t > 0)
            accum<32>(acc2, g_h2T + ((t - 1) & 1) * HB + (size_t)(ks * 32) * BATCH,
                      ws2T + (HID + ks * 32) * 8, rg, bgoff);
        bar_wait(&g_s1, base1 + t + 1);

        // ---- layer-2 dependent part: h1(t) ----
        accum<32>(acc2, g_h1T + (t & 1) * HB + (size_t)(ks * 32) * BATCH,
                  ws2T + (ks * 32) * 8, rg, bgoff);
        dump_stage(stage, acc2, ks, rg, bgoff);
        __syncthreads();
        if (tid < 128) {
            int jj = tid >> 6, b = tid & 63;
            float gv[4];
#pragma unroll
            for (int g = 0; g < 4; g++) {
                float s = bias2[g * 2 + jj];
#pragma unroll
                for (int w = 0; w < KSPLIT; w++) s += stage[(w * 8 + g * 2 + jj) * STAGE_S + b];
                gv[g] = s;
            }
            float c = fsig(gv[1]) * c2[tid] + fsig(gv[0]) * ftanh(gv[2]);
            c2[tid] = c;
            float h = fsig(gv[3]) * ftanh(c);
            g_h2T[(t & 1) * HB + (size_t)(j0 + jj) * BATCH + b] = h;
            outred[jj * 66 + b] = h * wout_s[jj];
        }
        __syncthreads();
        if (tid < 64) {
            float v = outred[tid] + outred[66 + tid];
            atomicAdd(&g_outacc[t * BATCH + tid], v);
        }
        bar_arrive(&g_c2, &g_s2);

        // ---- next step's independent part: x(t+1) (hides bar2 wait) ----
#pragma unroll
        for (int i = 0; i < 8; i++) acc1[i] = 0ull;
        if (t + 1 < T_STEPS)
            accum<16>(acc1, g_xT + (size_t)(t + 1) * IN_DIM * BATCH + (size_t)(ks * 16) * BATCH,
                      ws1T + (ks * 16) * 8, rg, bgoff);
        bar_wait(&g_s2, base2 + t + 1);
    }

    // ---- final: all REDs visible everywhere, then fused output head ----
    __threadfence();
    __syncthreads();
    bar_arrive(&g_c0, &g_s0);
    bar_wait(&g_s0, base0 + 2);
    {
        int i0 = blockIdx.x * 512 + tid;
        out[i0] = fsig(__ldcg(&g_outacc[i0]) + bout[0]);
    }
}

extern "C" void kernel_launch(void* const* d_in, const int* in_sizes, int n_in,
                              void* d_out, int out_size) {
    const float* input = (const float*)d_in[0];
    const float* Wih1 = (const float*)d_in[1];
    const float* Whh1 = (const float*)d_in[2];
    const float* bih1 = (const float*)d_in[3];
    const float* bhh1 = (const float*)d_in[4];
    const float* Wih2 = (const float*)d_in[5];
    const float* Whh2 = (const float*)d_in[6];
    const float* bih2 = (const float*)d_in[7];
    const float* bhh2 = (const float*)d_in[8];
    const float* Wout = (const float*)d_in[9];
    const float* bout = (const float*)d_in[10];

    int smem_bytes = SMEM_FLOATS * (int)sizeof(float);   // ~92.8 KB -> 2 CTAs/SM
    cudaFuncSetAttribute(lstm_all,
                         cudaFuncAttributeMaxDynamicSharedMemorySize, smem_bytes);
    lstm_all<<<NCTA, NTHREADS, smem_bytes>>>(
        input, Wih1, Whh1, bih1, bhh1, Wih2, Whh2, bih2, bhh2,
        Wout, bout, (float*)d_out);
}